// round 14
// baseline (speedup 1.0000x reference)
#include <cuda_runtime.h>

// 5x5 box-filter mean, reflect padding, NCHW fp32, H=W=512.
// R14 = R11 per-thread dataflow (128-thr CTAs, 4 out rows / 8 in rows,
// vertical tree partials, deferred halo, shuffle horizontal) SOFTWARE-
// PIPELINED over two z-planes per CTA:
//   load A -> vsum A (c_A dies) -> load B (8 LDG in flight) ->
//   halo/shuffle/store A (overlaps B loads) -> vsum/halo/shuffle/store B.

#define IMG 512
#define TW  128   // tile width  (floats) = 32 lanes * 4
#define TH  16    // tile height (rows)   = 4 warps * 4

__device__ __forceinline__ int refl(int x) {
    return (x < 0) ? -x : ((x >= IMG) ? (2 * IMG - 2 - x) : x);
}

struct V4 { float4 v[4]; };
struct VE { float2 e[4]; };

__device__ __forceinline__ void load_rows(const float* __restrict__ img,
                                          int rbase, int colx, bool interior_y,
                                          float4 (&c)[8])
{
    if (interior_y) {
        const float* p = img + rbase * IMG + colx;
        #pragma unroll
        for (int k = 0; k < 8; k++)
            c[k] = *reinterpret_cast<const float4*>(p + k * IMG);
    } else {
        #pragma unroll
        for (int k = 0; k < 8; k++)
            c[k] = *reinterpret_cast<const float4*>(img + refl(rbase + k) * IMG + colx);
    }
}

__device__ __forceinline__ V4 vsum(const float4 (&c)[8])
{
    float4 a, b, d;
    a.x = c[1].x + c[2].x;  a.y = c[1].y + c[2].y;  a.z = c[1].z + c[2].z;  a.w = c[1].w + c[2].w;
    b.x = c[3].x + c[4].x;  b.y = c[3].y + c[4].y;  b.z = c[3].z + c[4].z;  b.w = c[3].w + c[4].w;
    d.x = c[5].x + c[6].x;  d.y = c[5].y + c[6].y;  d.z = c[5].z + c[6].z;  d.w = c[5].w + c[6].w;
    V4 r;
    r.v[0].x = c[0].x + a.x + b.x;  r.v[0].y = c[0].y + a.y + b.y;
    r.v[0].z = c[0].z + a.z + b.z;  r.v[0].w = c[0].w + a.w + b.w;
    r.v[1].x = a.x + b.x + c[5].x;  r.v[1].y = a.y + b.y + c[5].y;
    r.v[1].z = a.z + b.z + c[5].z;  r.v[1].w = a.w + b.w + c[5].w;
    r.v[2].x = c[2].x + b.x + d.x;  r.v[2].y = c[2].y + b.y + d.y;
    r.v[2].z = c[2].z + b.z + d.z;  r.v[2].w = c[2].w + b.w + d.w;
    r.v[3].x = b.x + d.x + c[7].x;  r.v[3].y = b.y + d.y + c[7].y;
    r.v[3].z = b.z + d.z + c[7].z;  r.v[3].w = b.w + d.w + c[7].w;
    return r;
}

__device__ __forceinline__ VE halo_vsum(const float* __restrict__ img,
                                        int rbase, int tile_x, bool interior_y,
                                        int lane)
{
    VE r;
    #pragma unroll
    for (int k = 0; k < 4; k++) { r.e[k].x = 0.f; r.e[k].y = 0.f; }
    if (lane == 0 || lane == 31) {
        const bool left = (lane == 0);
        float2 e[8];
        if (left) {
            if (tile_x == 0) {
                #pragma unroll
                for (int k = 0; k < 8; k++) {          // reflect: -2 -> 2, -1 -> 1
                    const float* rp = img + refl(rbase + k) * IMG;
                    e[k].x = rp[2];
                    e[k].y = rp[1];
                }
            } else if (interior_y) {
                const float* p = img + rbase * IMG + tile_x - 2;
                #pragma unroll
                for (int k = 0; k < 8; k++)
                    e[k] = *reinterpret_cast<const float2*>(p + k * IMG);
            } else {
                #pragma unroll
                for (int k = 0; k < 8; k++)
                    e[k] = *reinterpret_cast<const float2*>(
                        img + refl(rbase + k) * IMG + tile_x - 2);
            }
        } else {
            if (tile_x + TW == IMG) {
                #pragma unroll
                for (int k = 0; k < 8; k++) {          // reflect: 512 -> 510, 513 -> 509
                    const float* rp = img + refl(rbase + k) * IMG;
                    e[k].x = rp[IMG - 2];
                    e[k].y = rp[IMG - 3];
                }
            } else if (interior_y) {
                const float* p = img + rbase * IMG + tile_x + TW;
                #pragma unroll
                for (int k = 0; k < 8; k++)
                    e[k] = *reinterpret_cast<const float2*>(p + k * IMG);
            } else {
                #pragma unroll
                for (int k = 0; k < 8; k++)
                    e[k] = *reinterpret_cast<const float2*>(
                        img + refl(rbase + k) * IMG + tile_x + TW);
            }
        }
        float2 ae, be, de;
        ae.x = e[1].x + e[2].x;  ae.y = e[1].y + e[2].y;
        be.x = e[3].x + e[4].x;  be.y = e[3].y + e[4].y;
        de.x = e[5].x + e[6].x;  de.y = e[5].y + e[6].y;
        r.e[0].x = e[0].x + ae.x + be.x;  r.e[0].y = e[0].y + ae.y + be.y;
        r.e[1].x = ae.x + be.x + e[5].x;  r.e[1].y = ae.y + be.y + e[5].y;
        r.e[2].x = e[2].x + be.x + de.x;  r.e[2].y = e[2].y + be.y + de.y;
        r.e[3].x = be.x + de.x + e[7].x;  r.e[3].y = be.y + de.y + e[7].y;
    }
    return r;
}

__device__ __forceinline__ void shuffle_store(const V4& vv, const VE& ve,
                                              float* obase, int lane)
{
    const float inv25 = 1.0f / 25.0f;
    #pragma unroll
    for (int r = 0; r < 4; r++) {
        const float4 v = vv.v[r];
        float pz = __shfl_up_sync(0xffffffffu, v.z, 1);   // col -2
        float pw = __shfl_up_sync(0xffffffffu, v.w, 1);   // col -1
        float nx = __shfl_down_sync(0xffffffffu, v.x, 1); // col +4
        float ny = __shfl_down_sync(0xffffffffu, v.y, 1); // col +5
        if (lane == 0)  { pz = ve.e[r].x; pw = ve.e[r].y; }
        if (lane == 31) { nx = ve.e[r].x; ny = ve.e[r].y; }

        const float s = v.x + v.y + v.z + v.w;
        float4 o;
        o.x = ((s - v.w) + pz + pw) * inv25;   // cols -2..2
        o.y = (s + pw) * inv25;                // cols -1..3
        o.z = (s + nx) * inv25;                // cols  0..4
        o.w = ((s - v.x) + nx + ny) * inv25;   // cols  1..5
        *reinterpret_cast<float4*>(obase + r * IMG) = o;
    }
}

__global__ __launch_bounds__(128)
void box5_kernel(const float* __restrict__ in, float* __restrict__ out)
{
    const int lane = threadIdx.x;       // 0..31 -> float4 column
    const int wrp  = threadIdx.y;       // 0..3  -> 4-row group

    const int tile_x = blockIdx.x * TW;
    const int tile_y = blockIdx.y * TH;
    const size_t planeA = (size_t)(blockIdx.z * 2) * (IMG * IMG);
    const float* __restrict__ imgA  = in  + planeA;
    const float* __restrict__ imgB  = imgA + IMG * IMG;
    float* __restrict__ oimgA = out + planeA;
    float* __restrict__ oimgB = oimgA + IMG * IMG;

    const int colx  = tile_x + lane * 4;
    const int rbase = tile_y + wrp * 4 - 2;   // first of 8 input rows
    const bool interior_y = (rbase >= 0) && (rbase + 7 < IMG);

    float* obaseA = oimgA + (tile_y + wrp * 4) * IMG + colx;
    float* obaseB = oimgB + (tile_y + wrp * 4) * IMG + colx;

    // ---- Phase A loads + vsum (c dies) ----
    float4 cA[8];
    load_rows(imgA, rbase, colx, interior_y, cA);
    V4 vA = vsum(cA);

    // ---- Phase B loads issued here: in flight during A's tail ----
    float4 cB[8];
    load_rows(imgB, rbase, colx, interior_y, cB);

    // ---- A tail: halo (L1 hits), shuffles, stores ----
    VE veA = halo_vsum(imgA, rbase, tile_x, interior_y, lane);
    shuffle_store(vA, veA, obaseA, lane);

    // ---- B: vsum, halo, shuffles, stores ----
    V4 vB = vsum(cB);
    VE veB = halo_vsum(imgB, rbase, tile_x, interior_y, lane);
    shuffle_store(vB, veB, obaseB, lane);
}

extern "C" void kernel_launch(void* const* d_in, const int* in_sizes, int n_in,
                              void* d_out, int out_size)
{
    const float* in = (const float*)d_in[0];
    float* out = (float*)d_out;

    const int planes = in_sizes[0] / (IMG * IMG);   // 96

    dim3 grid(IMG / TW, IMG / TH, planes / 2);      // (4, 32, 48)
    dim3 block(32, 4);
    box5_kernel<<<grid, block>>>(in, out);
}